// round 2
// baseline (speedup 1.0000x reference)
#include <cuda_runtime.h>
#include <cstdint>

// LSTM: IN=14, H=28, OUT=2, B=4096, T=512
// Two warps per sequence (64-thread block). Lane j (0..27) of warp0 owns gate
// rows i_j and g_j; warp1 owns f_j and o_j. Halving per-lane register weights
// (42 u64 vs 84) doubles occupancy so the fma pipe stays fed through the
// per-step serial tail. Exchange p = sigm(i)*tanh(g) and h via smem + bars.
// Packed fma.rn.f32x2 (2 MACs/slot, rt=2) for all gate math.

#define IN_DIM 14
#define HID    28
#define TSTEPS 512
#define BATCH  4096

typedef unsigned long long u64;

__device__ __forceinline__ u64 pack2(float lo, float hi) {
    u64 r; asm("mov.b64 %0, {%1, %2};" : "=l"(r) : "f"(lo), "f"(hi)); return r;
}
__device__ __forceinline__ void unpack2(u64 v, float& lo, float& hi) {
    asm("mov.b64 {%0, %1}, %2;" : "=f"(lo), "=f"(hi) : "l"(v));
}
__device__ __forceinline__ void ffma2(u64& acc, u64 a, u64 b) {
    asm("fma.rn.f32x2 %0, %1, %2, %0;" : "+l"(acc) : "l"(a), "l"(b));
}
__device__ __forceinline__ float fast_ex2(float x) {
    float r; asm("ex2.approx.f32 %0, %1;" : "=f"(r) : "f"(x)); return r;
}
__device__ __forceinline__ float fast_rcp(float x) {
    float r; asm("rcp.approx.f32 %0, %1;" : "=f"(r) : "f"(x)); return r;
}
// sigmoid(x) = 1 / (1 + 2^(-x*log2e))
__device__ __forceinline__ float sigm(float x) {
    return fast_rcp(1.0f + fast_ex2(-1.4426950408889634f * x));
}
// tanh(x) = 2/(1 + 2^(-2x*log2e)) - 1
__device__ __forceinline__ float tanh_f(float x) {
    return fmaf(2.0f, fast_rcp(1.0f + fast_ex2(-2.8853900817779268f * x)), -1.0f);
}

__global__ void __launch_bounds__(64, 7)
lstm_kernel(const float* __restrict__ x,
            const float* __restrict__ W_ih,
            const float* __restrict__ W_hh,
            const float* __restrict__ b_ih,
            const float* __restrict__ b_hh,
            const float* __restrict__ W_out,
            const float* __restrict__ b_out,
            float* __restrict__ out)
{
    const int seq  = blockIdx.x;            // 4096 blocks = 4096 sequences
    const int tid  = threadIdx.x;           // 64 threads = 2 warps
    const int lane = tid & 31;
    const int wrp  = tid >> 5;              // 0 or 1
    const int j    = (lane < HID) ? lane : (HID - 1);  // lanes 28..31 mirror 27

    // Gate rows (PyTorch order i,f,g,o): warp0 -> i (0) and g (2);
    //                                    warp1 -> f (1) and o (3).
    const int ga = wrp;          // gate index for accumulator A0
    const int gb = wrp + 2;      // gate index for accumulator A1
    const int r0 = ga * HID + j;
    const int r1 = gb * HID + j;

    // ---- register-resident weights (f32x2 pairs over k), 42 u64 per lane ----
    u64 wi0[IN_DIM / 2], wi1[IN_DIM / 2];   // 7 + 7
    u64 wh0[HID / 2],    wh1[HID / 2];      // 14 + 14
    {
        const u64* a = (const u64*)(W_ih + r0 * IN_DIM);
        const u64* b = (const u64*)(W_ih + r1 * IN_DIM);
#pragma unroll
        for (int p = 0; p < IN_DIM / 2; p++) { wi0[p] = a[p]; wi1[p] = b[p]; }
        const u64* c = (const u64*)(W_hh + r0 * HID);
        const u64* d = (const u64*)(W_hh + r1 * HID);
#pragma unroll
        for (int p = 0; p < HID / 2; p++) { wh0[p] = c[p]; wh1[p] = d[p]; }
    }
    const u64 bp0 = pack2(b_ih[r0] + b_hh[r0], 0.0f);
    const u64 bp1 = pack2(b_ih[r1] + b_hh[r1], 0.0f);

    __shared__ __align__(16) float hs[32];   // h broadcast
    __shared__ __align__(16) float ps[32];   // p = sigm(i)*tanh(g) exchange
    if (tid < 32) hs[tid] = 0.0f;
    float c = 0.0f, h = 0.0f;
    __syncthreads();

    // x for this sequence: 512 steps * 7 u64 pairs, contiguous
    const u64* xq = (const u64*)(x + (size_t)seq * TSTEPS * IN_DIM);
    u64 xc[7];
#pragma unroll
    for (int p = 0; p < 7; p++) xc[p] = xq[p];

    float fa = 0.0f, oa = 0.0f;

#pragma unroll 1
    for (int t = 0; t < TSTEPS; t++) {
        // prefetch next step's x (uniform address -> L1 broadcast)
        u64 xn[7];
        {
            const int tn = (t + 1 < TSTEPS) ? (t + 1) : (TSTEPS - 1);
            const u64* xr = xq + tn * 7;
#pragma unroll
            for (int p = 0; p < 7; p++) xn[p] = xr[p];
        }

        // gate pre-activations: lo half = even-k (+bias), hi half = odd-k
        u64 A0 = bp0, A1 = bp1;
#pragma unroll
        for (int p = 0; p < IN_DIM / 2; p++) {
            ffma2(A0, wi0[p], xc[p]);
            ffma2(A1, wi1[p], xc[p]);
        }
#pragma unroll
        for (int q = 0; q < HID / 2; q++) {
            u64 hv = *(const u64*)(hs + 2 * q);   // LDS.64 broadcast
            ffma2(A0, wh0[q], hv);
            ffma2(A1, wh1[q], hv);
        }
        float lo, hi;
        unpack2(A0, lo, hi); const float pre0 = lo + hi;
        unpack2(A1, lo, hi); const float pre1 = lo + hi;

        if (wrp == 0) {
            // p_j = sigm(i) * tanh(g)
            ps[lane] = sigm(pre0) * tanh_f(pre1);
        } else {
            fa = sigm(pre0);   // forget gate
            oa = sigm(pre1);   // output gate
        }
        __syncthreads();          // ps visible; all hs reads of this step done
        if (wrp == 1) {
            c = fmaf(fa, c, ps[j]);
            h = oa * tanh_f(c);
            hs[lane] = h;         // lanes 28..31 write dup to hs[28..31] (never read)
        }
        __syncthreads();          // new h visible

#pragma unroll
        for (int p = 0; p < 7; p++) xc[p] = xn[p];
    }

    // out[seq, o] = sum_j h_j * W_out[o, j] + b_out[o]   (warp1 holds h)
    if (wrp == 1) {
        const float w0 = (lane < HID) ? W_out[lane]       : 0.0f;
        const float w1 = (lane < HID) ? W_out[HID + lane] : 0.0f;
        float v0 = h * w0;
        float v1 = h * w1;
#pragma unroll
        for (int off = 16; off; off >>= 1) {
            v0 += __shfl_down_sync(0xffffffffu, v0, off);
            v1 += __shfl_down_sync(0xffffffffu, v1, off);
        }
        if (lane == 0) {
            out[seq * 2 + 0] = v0 + b_out[0];
            out[seq * 2 + 1] = v1 + b_out[1];
        }
    }
}

extern "C" void kernel_launch(void* const* d_in, const int* in_sizes, int n_in,
                              void* d_out, int out_size)
{
    const float* x     = (const float*)d_in[0];
    const float* W_ih  = (const float*)d_in[1];
    const float* W_hh  = (const float*)d_in[2];
    const float* b_ih  = (const float*)d_in[3];
    const float* b_hh  = (const float*)d_in[4];
    const float* W_out = (const float*)d_in[5];
    const float* b_out = (const float*)d_in[6];
    float* out = (float*)d_out;

    lstm_kernel<<<BATCH, 64>>>(x, W_ih, W_hh, b_ih, b_hh, W_out, b_out, out);
}